// round 5
// baseline (speedup 1.0000x reference)
#include <cuda_runtime.h>

#define Bsz 128
#define Hdim 256
#define Wdim 1024
#define N_HOLES 5
#define PROB 1.0f
#define HOLE_MINW (Wdim / 10)              // 102
#define HOLE_MINH (Hdim / 10)              // 25
#define N_TOTAL ((long long)Bsz * Hdim * Wdim)   // 33,554,432

#define GRID 592                           // 148 SMs * 4 -> all co-resident
#define NT 256

__device__ float g_partials[GRID];
__device__ float g_mean;
__device__ int   g_count = 0;              // last block resets -> replay-safe
__device__ int   g_epoch = 0;              // monotonic: bumps once per launch

// Single fused kernel:
//  phase 1: grid-stride copy x->out + per-block partial sums
//  sync:    ticket counter; last block reduces partials -> g_mean, bumps epoch
//  phase 2: every block fills its holes with g_mean (vectorized rect sweep)
__global__ void __launch_bounds__(NT, 4) fused_cutout_kernel(
    const float4* __restrict__ x, float4* __restrict__ out,
    const int* __restrict__ xs, const int* __restrict__ ys,
    const int* __restrict__ xs_w_raw, const int* __restrict__ ys_h_raw,
    const float* __restrict__ act_rand)
{
    // Read epoch before any block could possibly bump it (bump requires all
    // GRID tickets; our ticket comes after this read + __syncthreads).
    const int epoch0 = *(volatile int*)&g_epoch;

    // ---- phase 1: copy + reduce ----
    const long long n4 = N_TOTAL / 4;
    long long i = (long long)blockIdx.x * NT + threadIdx.x;
    const long long stride = (long long)GRID * NT;
    float s = 0.0f;
    #pragma unroll 4
    for (; i < n4; i += stride) {
        float4 v = x[i];
        out[i] = v;
        s += (v.x + v.y) + (v.z + v.w);
    }

    #pragma unroll
    for (int o = 16; o > 0; o >>= 1)
        s += __shfl_down_sync(0xFFFFFFFFu, s, o);
    __shared__ float ws[8];
    const int lane = threadIdx.x & 31, warp = threadIdx.x >> 5;
    if (lane == 0) ws[warp] = s;
    __syncthreads();
    __shared__ int is_last;
    if (threadIdx.x == 0) {
        float v = ws[0];
        #pragma unroll
        for (int k = 1; k < 8; ++k) v += ws[k];
        g_partials[blockIdx.x] = v;
        __threadfence();
        int ticket = atomicAdd(&g_count, 1);
        is_last = (ticket == GRID - 1);
    }
    __syncthreads();

    if (is_last) {
        double s2 = 0.0;
        for (int k = threadIdx.x; k < GRID; k += NT)
            s2 += (double)g_partials[k];
        #pragma unroll
        for (int o = 16; o > 0; o >>= 1)
            s2 += __shfl_down_sync(0xFFFFFFFFu, s2, o);
        __shared__ double wd[8];
        if (lane == 0) wd[warp] = s2;
        __syncthreads();
        if (threadIdx.x == 0) {
            double t = wd[0];
            #pragma unroll
            for (int k = 1; k < 8; ++k) t += wd[k];
            g_mean = (float)(t / (double)N_TOTAL);
            g_count = 0;                   // reset for next replay
            __threadfence();
            *(volatile int*)&g_epoch = epoch0 + 1;   // release
        }
    }

    // ---- grid-wide sync: thread 0 spins, block follows ----
    if (threadIdx.x == 0) {
        while (*(volatile int*)&g_epoch == epoch0)
            __nanosleep(64);
    }
    __syncthreads();
    __threadfence();                       // acquire
    const float fill = *(volatile float*)&g_mean;
    const float4 f4 = make_float4(fill, fill, fill, fill);

    // ---- phase 2: fill holes ----
    const int qx = threadIdx.x & 63;       // quad lane
    const int ry = threadIdx.x >> 6;       // row lane (0..3)

    for (int hole = blockIdx.x; hole < Bsz * N_HOLES; hole += GRID) {
        if (!(act_rand[hole] < PROB)) continue;
        const int b = hole / N_HOLES;

        const int hw = xs_w_raw[hole] + HOLE_MINW;
        const int hh = ys_h_raw[hole] + HOLE_MINH;
        const int cw = xs[hole], ch = ys[hole];
        const int x0 = min(max(cw - hw / 2, 0), Wdim - 2);
        const int x1 = min(max(cw + hw / 2, 1), Wdim - 1);
        const int y0 = min(max(ch - hh / 2, 0), Hdim - 2);
        const int y1 = min(max(ch + hh / 2, 1), Hdim - 1);

        const int a0 = (x0 + 3) & ~3;      // first aligned float index
        const int a1 = (x1 + 1) & ~3;      // exclusive aligned end
        const int nvec = (a1 - a0) >> 2;   // float4 interior count

        const int wl = x0 + qx;            // left-edge scalar (qx < 3)
        const bool do_l = (qx < 3) && (wl < a0);
        const int wr = a1 + (qx - 3);      // right-edge scalar (qx in [3,6))
        const bool do_r = (qx >= 3) && (qx < 6) && (wr <= x1);

        float* const base = (float*)out + (size_t)b * Hdim * Wdim + a0;
        for (int h = y0 + ry; h <= y1; h += 4) {
            float* const row = base + (size_t)h * Wdim;
            if (do_l) row[wl - a0] = fill;
            if (do_r) row[wr - a0] = fill;
            float4* const rowv = reinterpret_cast<float4*>(row);
            for (int q = qx; q < nvec; q += 64)
                rowv[q] = f4;
        }
    }
}

extern "C" void kernel_launch(void* const* d_in, const int* in_sizes, int n_in,
                              void* d_out, int out_size) {
    const float* x        = (const float*)d_in[0];
    const int*   xs       = (const int*)d_in[1];
    const int*   ys       = (const int*)d_in[2];
    const int*   xs_w_raw = (const int*)d_in[3];
    const int*   ys_h_raw = (const int*)d_in[4];
    const float* act_rand = (const float*)d_in[5];
    float* out = (float*)d_out;

    fused_cutout_kernel<<<GRID, NT>>>((const float4*)x, (float4*)out,
                                      xs, ys, xs_w_raw, ys_h_raw, act_rand);
}